// round 8
// baseline (speedup 1.0000x reference)
#include <cuda_runtime.h>
#include <cuda_bf16.h>
#include <math.h>
#include <stdint.h>

#define T_TOK 8192
#define D_DIM 1024
#define E_NUM 8
#define IMOE  1024
#define ISH   4096

// ---------------- scratch (device globals) ----------------
__device__ __align__(256) __nv_bfloat16 g_xh[(size_t)T_TOK * D_DIM];
__device__ __align__(256) __nv_bfloat16 g_xl[(size_t)T_TOK * D_DIM];
__device__ __align__(256) __nv_bfloat16 g_sgT_h[(size_t)ISH * D_DIM];
__device__ __align__(256) __nv_bfloat16 g_sgT_l[(size_t)ISH * D_DIM];
__device__ __align__(256) __nv_bfloat16 g_suT_h[(size_t)ISH * D_DIM];
__device__ __align__(256) __nv_bfloat16 g_suT_l[(size_t)ISH * D_DIM];
__device__ __align__(256) __nv_bfloat16 g_sdT_h[(size_t)D_DIM * ISH];
__device__ __align__(256) __nv_bfloat16 g_sdT_l[(size_t)D_DIM * ISH];
__device__ __align__(256) __nv_bfloat16 g_egT_h[(size_t)E_NUM * IMOE * D_DIM];
__device__ __align__(256) __nv_bfloat16 g_egT_l[(size_t)E_NUM * IMOE * D_DIM];
__device__ __align__(256) __nv_bfloat16 g_euT_h[(size_t)E_NUM * IMOE * D_DIM];
__device__ __align__(256) __nv_bfloat16 g_euT_l[(size_t)E_NUM * IMOE * D_DIM];
__device__ __align__(256) __nv_bfloat16 g_edT_h[(size_t)E_NUM * D_DIM * IMOE];
__device__ __align__(256) __nv_bfloat16 g_edT_l[(size_t)E_NUM * D_DIM * IMOE];
__device__ __align__(256) __nv_bfloat16 g_hshh[(size_t)T_TOK * ISH];
__device__ __align__(256) __nv_bfloat16 g_hshl[(size_t)T_TOK * ISH];
__device__ __align__(256) __nv_bfloat16 g_heh[(size_t)E_NUM * T_TOK * IMOE];
__device__ __align__(256) __nv_bfloat16 g_hel[(size_t)E_NUM * T_TOK * IMOE];

__device__ int   g_cnt[E_NUM];
__device__ int   g_tok[E_NUM * T_TOK];
__device__ float g_wt [E_NUM * T_TOK];
__device__ float g_sgate[T_TOK];

// ---------------- helpers ----------------
__device__ __forceinline__ uint32_t smem_u32(const void* p) {
    return (uint32_t)__cvta_generic_to_shared(p);
}
__device__ __forceinline__ void cp16(uint32_t dst, const void* src) {
    asm volatile("cp.async.cg.shared.global [%0], [%1], 16;" :: "r"(dst), "l"(src));
}
#define CP_COMMIT() asm volatile("cp.async.commit_group;")
#define CP_WAIT1()  asm volatile("cp.async.wait_group 1;")
__device__ __forceinline__ void ldm_x4(uint32_t* r, uint32_t addr) {
    asm volatile("ldmatrix.sync.aligned.m8n8.x4.shared.b16 {%0,%1,%2,%3}, [%4];"
                 : "=r"(r[0]), "=r"(r[1]), "=r"(r[2]), "=r"(r[3]) : "r"(addr));
}
__device__ __forceinline__ void mma_bf16(float* d, const uint32_t* a, const uint32_t* b) {
    asm volatile("mma.sync.aligned.m16n8k16.row.col.f32.bf16.bf16.f32 "
                 "{%0,%1,%2,%3}, {%4,%5,%6,%7}, {%8,%9}, {%0,%1,%2,%3};"
                 : "+f"(d[0]), "+f"(d[1]), "+f"(d[2]), "+f"(d[3])
                 : "r"(a[0]), "r"(a[1]), "r"(a[2]), "r"(a[3]), "r"(b[0]), "r"(b[1]));
}
__device__ __forceinline__ void bf_split(float v, __nv_bfloat16& h, __nv_bfloat16& l) {
    h = __float2bfloat16(v);
    l = __float2bfloat16(v - __bfloat162float(h));
}
__device__ __forceinline__ uint32_t pack2(__nv_bfloat16 a, __nv_bfloat16 b) {
    return ((uint32_t)__bfloat16_as_ushort(b) << 16) | __bfloat16_as_ushort(a);
}

// ---------------- routing ----------------
__global__ void zero_counts_kernel() {
    if (threadIdx.x < E_NUM) g_cnt[threadIdx.x] = 0;
}

__global__ void router_kernel(const float* __restrict__ x,
                              const float* __restrict__ gw,
                              const float* __restrict__ sgw,
                              float* __restrict__ logits_out) {
    int t = (int)((blockIdx.x * blockDim.x + threadIdx.x) >> 5);
    int lane = threadIdx.x & 31;
    if (t >= T_TOK) return;
    const float* xr = x + (size_t)t * D_DIM;
    float acc[E_NUM];
#pragma unroll
    for (int e = 0; e < E_NUM; e++) acc[e] = 0.f;
    float sg = 0.f;
    for (int k = lane; k < D_DIM; k += 32) {
        float xv = xr[k];
#pragma unroll
        for (int e = 0; e < E_NUM; e++) acc[e] = fmaf(xv, gw[k * E_NUM + e], acc[e]);
        sg = fmaf(xv, sgw[k], sg);
    }
#pragma unroll
    for (int o = 16; o; o >>= 1) {
#pragma unroll
        for (int e = 0; e < E_NUM; e++) acc[e] += __shfl_xor_sync(0xffffffffu, acc[e], o);
        sg += __shfl_xor_sync(0xffffffffu, sg, o);
    }
    if (lane == 0) {
        float m = acc[0];
#pragma unroll
        for (int e = 1; e < E_NUM; e++) m = fmaxf(m, acc[e]);
        float p[E_NUM];
#pragma unroll
        for (int e = 0; e < E_NUM; e++) {
            p[e] = expf(acc[e] - m);
            logits_out[t * E_NUM + e] = acc[e];
        }
        int i0 = 0;
#pragma unroll
        for (int e = 1; e < E_NUM; e++) if (p[e] > p[i0]) i0 = e;
        int i1 = -1;
        float best = -1.f;
#pragma unroll
        for (int e = 0; e < E_NUM; e++) {
            if (e == i0) continue;
            if (p[e] > best) { best = p[e]; i1 = e; }
        }
        float s = p[i0] + p[i1];
        float w0 = p[i0] / s, w1 = p[i1] / s;
        int p0 = atomicAdd(&g_cnt[i0], 1);
        g_tok[i0 * T_TOK + p0] = t; g_wt[i0 * T_TOK + p0] = w0;
        int p1 = atomicAdd(&g_cnt[i1], 1);
        g_tok[i1 * T_TOK + p1] = t; g_wt[i1 * T_TOK + p1] = w1;
        g_sgate[t] = 1.f / (1.f + expf(-sg));
    }
}

// ---------------- conversions ----------------
__global__ void split_x_kernel(const float* __restrict__ x,
                               __nv_bfloat16* __restrict__ oh,
                               __nv_bfloat16* __restrict__ ol) {
    size_t i = (size_t)blockIdx.x * blockDim.x + threadIdx.x;
    float4 v = reinterpret_cast<const float4*>(x)[i];
    __nv_bfloat16 h[4], l[4];
    bf_split(v.x, h[0], l[0]); bf_split(v.y, h[1], l[1]);
    bf_split(v.z, h[2], l[2]); bf_split(v.w, h[3], l[3]);
    uint2 ph, pl;
    ph.x = pack2(h[0], h[1]); ph.y = pack2(h[2], h[3]);
    pl.x = pack2(l[0], l[1]); pl.y = pack2(l[2], l[3]);
    reinterpret_cast<uint2*>(oh)[i] = ph;
    reinterpret_cast<uint2*>(ol)[i] = pl;
}

__global__ void tsplit_kernel(const float* __restrict__ in,
                              __nv_bfloat16* __restrict__ oh,
                              __nv_bfloat16* __restrict__ ol,
                              int K, int N) {
    __shared__ float t[32][33];
    size_t boff = (size_t)blockIdx.z * K * N;
    in += boff; oh += boff; ol += boff;
    int n0 = blockIdx.x * 32, k0 = blockIdx.y * 32;
    int tx = threadIdx.x, ty = threadIdx.y;
#pragma unroll
    for (int i = 0; i < 4; i++)
        t[ty + i * 8][tx] = in[(size_t)(k0 + ty + i * 8) * N + n0 + tx];
    __syncthreads();
#pragma unroll
    for (int i = 0; i < 4; i++) {
        float v = t[tx][ty + i * 8];
        __nv_bfloat16 h, l;
        bf_split(v, h, l);
        size_t o = (size_t)(n0 + ty + i * 8) * K + k0 + tx;
        oh[o] = h; ol[o] = l;
    }
}

// ---------------- GEMM geometry ----------------
// Tiles: row = 32 bf16 (64B) + 16B pad = 80B per row.
// up kernel stage: Ah(128)=10240, Al=10240, Bgh(64)=5120, Bgl, Buh, Bul -> 40960B
// down kernel stage: Ah(128), Al, Bh(128), Bl -> 40960B
#define STAGE_B  40960
#define NSTAGE   3
#define GEMM_SMEM (NSTAGE * STAGE_B)

// ===== Fused gate+up GEMM with SiLU epilogue =====
// C-tiles: G[128 x 64], U[128 x 64]; K = D_DIM (32 chunks of 32).
// 8 warps: wm = wid&3 (32 rows), wn = wid>>2 (32 cols).
__global__ __launch_bounds__(256, 1) void up_gemm(
        const __nv_bfloat16* __restrict__ Axh, const __nv_bfloat16* __restrict__ Axl,
        const __nv_bfloat16* __restrict__ Bgh_, const __nv_bfloat16* __restrict__ Bgl_,
        const __nv_bfloat16* __restrict__ Buh_, const __nv_bfloat16* __restrict__ Bul_,
        __nv_bfloat16* __restrict__ Hh_, __nv_bfloat16* __restrict__ Hl_,
        int hstride, int expertM) {
    extern __shared__ char dsm[];
    __shared__ int tok_s[128];
    const int tid = threadIdx.x, wid = tid >> 5, lane = tid & 31;
    const int m0 = blockIdx.y * 128, n0 = blockIdx.x * 64;
    const int e = blockIdx.z;
    int nrows = T_TOK;
    const __nv_bfloat16 *Bgh = Bgh_, *Bgl = Bgl_, *Buh = Buh_, *Bul = Bul_;
    __nv_bfloat16 *Hh = Hh_, *Hl = Hl_;
    if (expertM) {
        nrows = g_cnt[e];
        if (m0 >= nrows) return;
        size_t boff = (size_t)e * IMOE * D_DIM;
        Bgh += boff; Bgl += boff; Buh += boff; Bul += boff;
        size_t hoff = (size_t)e * T_TOK * IMOE;
        Hh += hoff; Hl += hoff;
    }
    if (tid < 128) {
        int row = m0 + tid;
        tok_s[tid] = expertM ? g_tok[e * T_TOK + (row < nrows ? row : nrows - 1)] : row;
    }
    __syncthreads();

    const int rA0 = tid >> 2, rA1 = rA0 + 64, c16 = tid & 3;
    const int a0 = tok_s[rA0], a1 = tok_s[rA1];
    const __nv_bfloat16* pAh0 = Axh + (size_t)a0 * D_DIM + c16 * 8;
    const __nv_bfloat16* pAh1 = Axh + (size_t)a1 * D_DIM + c16 * 8;
    const __nv_bfloat16* pAl0 = Axl + (size_t)a0 * D_DIM + c16 * 8;
    const __nv_bfloat16* pAl1 = Axl + (size_t)a1 * D_DIM + c16 * 8;
    const int rB = tid >> 2;
    const __nv_bfloat16* pBgh = Bgh + (size_t)(n0 + rB) * D_DIM + c16 * 8;
    const __nv_bfloat16* pBgl = Bgl + (size_t)(n0 + rB) * D_DIM + c16 * 8;
    const __nv_bfloat16* pBuh = Buh + (size_t)(n0 + rB) * D_DIM + c16 * 8;
    const __nv_bfloat16* pBul = Bul + (size_t)(n0 + rB) * D_DIM + c16 * 8;
    const uint32_t sbase = smem_u32(dsm);
    const uint32_t dA0 = rA0 * 80 + c16 * 16, dA1 = rA1 * 80 + c16 * 16;
    const uint32_t dB = rB * 80 + c16 * 16;

#define UP_ISSUE(stg, koff) do { \
    uint32_t sb_ = sbase + (stg) * STAGE_B; \
    cp16(sb_ + dA0, pAh0 + (koff)); cp16(sb_ + dA1, pAh1 + (koff)); \
    cp16(sb_ + 10240 + dA0, pAl0 + (koff)); cp16(sb_ + 10240 + dA1, pAl1 + (koff)); \
    cp16(sb_ + 20480 + dB, pBgh + (koff)); cp16(sb_ + 25600 + dB, pBgl + (koff)); \
    cp16(sb_ + 30720 + dB, pBuh + (koff)); cp16(sb_ + 35840 + dB, pBul + (koff)); \
} while (0)

    float accG[2][4][4], accU[2][4][4];
#pragma unroll
    for (int mi = 0; mi < 2; mi++)
#pragma unroll
        for (int ni = 0; ni < 4; ni++)
#pragma unroll
            for (int q = 0; q < 4; q++) { accG[mi][ni][q] = 0.f; accU[mi][ni][q] = 0.f; }

    const int wm = wid & 3, wn = wid >> 2;
    const uint32_t a_loff = (lane & 15) * 80 + (lane >> 4) * 16;
    const uint32_t b_loff = (((lane >> 4) & 1) * 8 + (lane & 7)) * 80 + ((lane >> 3) & 1) * 16;

    UP_ISSUE(0, 0); CP_COMMIT();
    UP_ISSUE(1, 32); CP_COMMIT();

    const int kchunks = D_DIM / 32;
    for (int ch = 0; ch < kchunks; ch++) {
        CP_WAIT1();
        __syncthreads();
        if (ch + 2 < kchunks) UP_ISSUE((ch + 2) % NSTAGE, (ch + 2) * 32);
        CP_COMMIT();

        uint32_t st = sbase + (ch % NSTAGE) * STAGE_B;
#pragma unroll
        for (int kk = 0; kk < 2; kk++) {
            uint32_t ak = a_loff + kk * 32;
            uint32_t bk = b_loff + kk * 32;
            uint32_t ah[2][4], al[2][4];
#pragma unroll
            for (int mi = 0; mi < 2; mi++) {
                uint32_t ro = (wm * 32 + mi * 16) * 80;
                ldm_x4(ah[mi], st + ro + ak);
                ldm_x4(al[mi], st + 10240 + ro + ak);
            }
            {   // gate
                uint32_t bh[4][2], bl[4][2];
#pragma unroll
                for (int nj = 0; nj < 2; nj++) {
                    uint32_t ro = (wn * 32 + nj * 16) * 80;
                    uint32_t t4[4];
                    ldm_x4(t4, st + 20480 + ro + bk);
                    bh[2 * nj][0] = t4[0]; bh[2 * nj][1] = t4[1];
                    bh[2 * nj + 1][0] = t4[2]; bh[2 * nj + 1][1] = t4[3];
                    ldm_x4(t4, st + 25600 + ro + bk);
                    bl[2 * nj][0] = t4[0]; bl[2 * nj][1] = t4[1];
                    bl[2 * nj + 1][0] = t4[2]; bl[2 * nj + 1][1] = t4[3];
                }
#pragma unroll
                for (int mi = 0; mi < 2; mi++)
#pragma unroll
                    for (int ni = 0; ni < 4; ni++) {
                        mma_bf16(accG[mi][ni], ah[mi], bh[ni]);
                        mma_bf16(accG[mi][ni], ah[mi], bl[ni]);
                        mma_bf16(accG[mi][ni], al[mi], bh[ni]);
                    }
            }
            {   // up
                uint32_t bh[4][2], bl[4][2];
#pragma unroll
                for (int nj = 0; nj < 2; nj++) {
                    uint32_t ro = (wn * 32 + nj * 16) * 80;
                    uint32_t t4[4];
                    ldm_x4(t4, st + 30720 + ro + bk);
                    bh[2 * nj][0] = t4[0]; bh[2 * nj][1] = t4[1];
                    bh[2 * nj + 1][0] = t4[2]; bh[2 * nj + 1][1] = t4[3];
                    ldm_x4(t4, st + 35840 + ro + bk);
                    bl[2 * nj][0] = t4[0]; bl[2 * nj][1] = t4[1];
                    bl[2 * nj + 1][0] = t4[2]; bl[2 * nj + 1][1] = t4[3];
                }
#pragma unroll
                for (int mi = 0; mi < 2; mi++)
#pragma unroll
                    for (int ni = 0; ni < 4; ni++) {
                        mma_bf16(accU[mi][ni], ah[mi], bh[ni]);
                        mma_bf16(accU[mi][ni], ah[mi], bl[ni]);
                        mma_bf16(accU[mi][ni], al[mi], bh[ni]);
                    }
            }
        }
        __syncthreads();
    }
#undef UP_ISSUE

    // SiLU epilogue: H = silu(G)*U, split to bf16 hi/lo, packed 4B stores
#pragma unroll
    for (int mi = 0; mi < 2; mi++) {
        int ra = m0 + wm * 32 + mi * 16 + (lane >> 2);
        int rc = ra + 8;
        bool v0 = ra < nrows, v1 = rc < nrows;
#pragma unroll
        for (int ni = 0; ni < 4; ni++) {
            int c = n0 + wn * 32 + ni * 8 + 2 * (lane & 3);
            float* G = accG[mi][ni];
            float* U = accU[mi][ni];
            if (v0) {
                float h0 = (G[0] / (1.f + __expf(-G[0]))) * U[0];
                float h1 = (G[1] / (1.f + __expf(-G[1]))) * U[1];
                __nv_bfloat16 a0h, a0l, a1h, a1l;
                bf_split(h0, a0h, a0l); bf_split(h1, a1h, a1l);
                size_t base = (size_t)ra * hstride + c;
                *(uint32_t*)(Hh + base) = pack2(a0h, a1h);
                *(uint32_t*)(Hl + base) = pack2(a0l, a1l);
            }
            if (v1) {
                float h2 = (G[2] / (1.f + __expf(-G[2]))) * U[2];
                float h3 = (G[3] / (1.f + __expf(-G[3]))) * U[3];
                __nv_bfloat16 a2h, a2l, a3h, a3l;
                bf_split(h2, a2h, a2l); bf_split(h3, a3h, a3l);
                size_t base = (size_t)rc * hstride + c;
                *(uint32_t*)(Hh + base) = pack2(a2h, a3h);
                *(uint32_t*)(Hl + base) = pack2(a2l, a3l);
            }
        }
    }
}

// ===== Down GEMM =====
// C[128 x 128]; 8 warps: wm = wid&1 (64 rows), wn = wid>>1 (32 cols).
// epi 1: out = sgate*acc (plain store). epi 2: atomicAdd(out[tok], wt*acc).
__global__ __launch_bounds__(256, 1) void down_gemm(
        const __nv_bfloat16* __restrict__ Ah_, const __nv_bfloat16* __restrict__ Al_,
        const __nv_bfloat16* __restrict__ Bh_, const __nv_bfloat16* __restrict__ Bl_,
        float* __restrict__ C,
        int lda, int kchunks, int epi, int expertM) {
    extern __shared__ char dsm[];
    const int tid = threadIdx.x, wid = tid >> 5, lane = tid & 31;
    const int m0 = blockIdx.y * 128, n0 = blockIdx.x * 128;
    const int e = blockIdx.z;
    int nrows = T_TOK;
    const int* tokp = nullptr;
    const float* wtp = nullptr;
    const __nv_bfloat16 *Ah = Ah_, *Al = Al_, *Bh = Bh_, *Bl = Bl_;
    if (expertM) {
        nrows = g_cnt[e];
        if (m0 >= nrows) return;
        tokp = g_tok + e * T_TOK;
        wtp  = g_wt  + e * T_TOK;
        size_t aoff = (size_t)e * T_TOK * IMOE;
        Ah += aoff; Al += aoff;
        size_t boff = (size_t)e * D_DIM * IMOE;
        Bh += boff; Bl += boff;
    }
    const int r0 = tid >> 2, r1 = r0 + 64, c16 = tid & 3;
    const int ar0 = (m0 + r0) < nrows ? (m0 + r0) : 0;
    const int ar1 = (m0 + r1) < nrows ? (m0 + r1) : 0;
    const __nv_bfloat16* pAh0 = Ah + (size_t)ar0 * lda + c16 * 8;
    const __nv_bfloat16* pAh1 = Ah + (size_t)ar1 * lda + c16 * 8;
    const __nv_bfloat16* pAl0 = Al + (size_t)ar0 * lda + c16 * 8;
    const __nv_bfloat16* pAl1 = Al + (size_t)ar1 * lda + c16 * 8;
    const __nv_bfloat16* pBh0 = Bh + (size_t)(n0 + r0) * lda + c16 * 8;
    const __nv_bfloat16* pBh1 = Bh + (size_t)(n0 + r1) * lda + c16 * 8;
    const __nv_bfloat16* pBl0 = Bl + (size_t)(n0 + r0) * lda + c16 * 8;
    const __nv_bfloat16* pBl1 = Bl + (size_t)(n0 + r1) * lda + c16 * 8;
    const uint32_t sbase = smem_u32(dsm);
    const uint32_t d0 = r0 * 80 + c16 * 16, d1 = r1 * 80 + c16 * 16;

#define DN_ISSUE(stg, koff) do { \
    uint32_t sb_ = sbase + (stg) * STAGE_B; \
    cp16(sb_ + d0, pAh0 + (koff)); cp16(sb_ + d1, pAh1 + (koff)); \
    cp16(sb_ + 10240 + d0, pAl0 + (koff)); cp16(sb_ + 10240 + d1, pAl1 + (koff)); \
    cp16(sb_ + 20480 + d0, pBh0 + (koff)); cp16(sb_ + 20480 + d1, pBh1 + (koff)); \
    cp16(sb_ + 30720 + d0, pBl0 + (koff)); cp16(sb_ + 30720 + d1, pBl1 + (koff)); \
} while (0)

    float acc[4][4][4];
#pragma unroll
    for (int mi = 0; mi < 4; mi++)
#pragma unroll
        for (int ni = 0; ni < 4; ni++)
#pragma unroll
            for (int q = 0; q < 4; q++) acc[mi][ni][q] = 0.f;

    const int wm = wid & 1, wn = wid >> 1;
    const uint32_t a_loff = (lane & 15) * 80 + (lane >> 4) * 16;
    const uint32_t b_loff = (((lane >> 4) & 1) * 8 + (lane & 7)) * 80 + ((lane >> 3) & 1) * 16;

    DN_ISSUE(0, 0); CP_COMMIT();
    DN_ISSUE(1, 32); CP_COMMIT();

    for (int ch = 0; ch < kchunks; ch++) {
        CP_WAIT1();
        __syncthreads();
        if (ch + 2 < kchunks) DN_ISSUE((ch + 2) % NSTAGE, (ch + 2) * 32);
        CP_COMMIT();

        uint32_t st = sbase + (ch % NSTAGE) * STAGE_B;
#pragma unroll
        for (int kk = 0; kk < 2; kk++) {
            uint32_t ah[4][4], al[4][4], bh[4][2], bl[4][2];
            uint32_t ak = a_loff + kk * 32;
            uint32_t bk = b_loff + kk * 32;
#pragma unroll
            for (int mi = 0; mi < 4; mi++) {
                uint32_t ro = (wm * 64 + mi * 16) * 80;
                ldm_x4(ah[mi], st + ro + ak);
                ldm_x4(al[mi], st + 10240 + ro + ak);
            }
#pragma unroll
            for (int nj = 0; nj < 2; nj++) {
                uint32_t ro = (wn * 32 + nj * 16) * 80;
                uint32_t t4[4];
                ldm_x4(t4, st + 20480 + ro + bk);
                bh[2 * nj][0] = t4[0]; bh[2 * nj][1] = t4[1];
                bh[2 * nj + 1][0] = t4[2]; bh[2 * nj + 1][1] = t4[3];
                ldm_x4(t4, st + 30720 + ro + bk);
                bl[2 * nj][0] = t4[0]; bl[2 * nj][1] = t4[1];
                bl[2 * nj + 1][0] = t4[2]; bl[2 * nj + 1][1] = t4[3];
            }
#pragma unroll
            for (int mi = 0; mi < 4; mi++)
#pragma unroll
                for (int ni = 0; ni < 4; ni++) {
                    mma_bf16(acc[mi][ni], ah[mi], bh[ni]);
                    mma_bf16(acc[mi][ni], ah[mi], bl[ni]);
                    mma_bf16(acc[mi][ni], al[mi], bh[ni]);
                }
        }
        __syncthreads();
    }
#undef DN_ISSUE

    const int rb = m0 + wm * 64, cb = n0 + wn * 32;
#pragma unroll
    for (int mi = 0; mi < 4; mi++) {
        int ra = rb + mi * 16 + (lane >> 2);
        int rc = ra + 8;
        if (epi == 1) {
            float s0 = g_sgate[ra], s1 = g_sgate[rc];
#pragma unroll
            for (int ni = 0; ni < 4; ni++) {
                int c = cb + ni * 8 + 2 * (lane & 3);
                float* d = acc[mi][ni];
                *(float2*)&C[(size_t)ra * D_DIM + c] = make_float2(s0 * d[0], s0 * d[1]);
                *(float2*)&C[(size_t)rc * D_DIM + c] = make_float2(s1 * d[2], s1 * d[3]);
            }
        } else {
            bool v0 = ra < nrows, v1 = rc < nrows;
            int t0 = 0, t1 = 0; float w0 = 0.f, w1 = 0.f;
            if (v0) { t0 = tokp[ra]; w0 = wtp[ra]; }
            if (v1) { t1 = tokp[rc]; w1 = wtp[rc]; }
#pragma unroll
            for (int ni = 0; ni < 4; ni++) {
                int c = cb + ni * 8 + 2 * (lane & 3);
                float* d = acc[mi][ni];
                if (v0) {
                    atomicAdd(&C[(size_t)t0 * D_DIM + c],     w0 * d[0]);
                    atomicAdd(&C[(size_t)t0 * D_DIM + c + 1], w0 * d[1]);
                }
                if (v1) {
                    atomicAdd(&C[(size_t)t1 * D_DIM + c],     w1 * d[2]);
                    atomicAdd(&C[(size_t)t1 * D_DIM + c + 1], w1 * d[3]);
                }
            }
        }
    }
}

// ---------------- launch ----------------
extern "C" void kernel_launch(void* const* d_in, const int* in_sizes, int n_in,
                              void* d_out, int out_size) {
    const float* x   = (const float*)d_in[0];
    const float* gw  = (const float*)d_in[1];
    const float* eg  = (const float*)d_in[2];
    const float* eu  = (const float*)d_in[3];
    const float* ed  = (const float*)d_in[4];
    const float* sg  = (const float*)d_in[5];
    const float* su  = (const float*)d_in[6];
    const float* sd  = (const float*)d_in[7];
    const float* sgw = (const float*)d_in[8];
    (void)in_sizes; (void)n_in;

    float* out    = (float*)d_out;
    float* logits = out + ((size_t)out_size - (size_t)T_TOK * E_NUM);

    static int smem_set = 0;
    if (!smem_set) {
        cudaFuncSetAttribute(up_gemm, cudaFuncAttributeMaxDynamicSharedMemorySize, GEMM_SMEM);
        cudaFuncSetAttribute(down_gemm, cudaFuncAttributeMaxDynamicSharedMemorySize, GEMM_SMEM);
        smem_set = 1;
    }

    __nv_bfloat16 *xh, *xl, *sgh, *sgl, *suh, *sul, *sdh, *sdl;
    __nv_bfloat16 *egh, *egl, *euh, *eul, *edh, *edl, *hsh, *hsl, *heh, *hel;
    cudaGetSymbolAddress((void**)&xh,  g_xh);    cudaGetSymbolAddress((void**)&xl,  g_xl);
    cudaGetSymbolAddress((void**)&sgh, g_sgT_h); cudaGetSymbolAddress((void**)&sgl, g_sgT_l);
    cudaGetSymbolAddress((void**)&suh, g_suT_h); cudaGetSymbolAddress((void**)&sul, g_suT_l);
    cudaGetSymbolAddress((void**)&sdh, g_sdT_h); cudaGetSymbolAddress((void**)&sdl, g_sdT_l);
    cudaGetSymbolAddress((void**)&egh, g_egT_h); cudaGetSymbolAddress((void**)&egl, g_egT_l);
    cudaGetSymbolAddress((void**)&euh, g_euT_h); cudaGetSymbolAddress((void**)&eul, g_euT_l);
    cudaGetSymbolAddress((void**)&edh, g_edT_h); cudaGetSymbolAddress((void**)&edl, g_edT_l);
    cudaGetSymbolAddress((void**)&hsh, g_hshh);  cudaGetSymbolAddress((void**)&hsl, g_hshl);
    cudaGetSymbolAddress((void**)&heh, g_heh);   cudaGetSymbolAddress((void**)&hel, g_hel);

    zero_counts_kernel<<<1, 32>>>();
    router_kernel<<<T_TOK / 8, 256>>>(x, gw, sgw, logits);

    split_x_kernel<<<(T_TOK * D_DIM / 4) / 256, 256>>>(x, xh, xl);
    dim3 tb(32, 8);
    tsplit_kernel<<<dim3(ISH / 32, D_DIM / 32, 1), tb>>>(sg, sgh, sgl, D_DIM, ISH);
    tsplit_kernel<<<dim3(ISH / 32, D_DIM / 32, 1), tb>>>(su, suh, sul, D_DIM, ISH);
    tsplit_kernel<<<dim3(D_DIM / 32, ISH / 32, 1), tb>>>(sd, sdh, sdl, ISH, D_DIM);
    tsplit_kernel<<<dim3(IMOE / 32, D_DIM / 32, E_NUM), tb>>>(eg, egh, egl, D_DIM, IMOE);
    tsplit_kernel<<<dim3(IMOE / 32, D_DIM / 32, E_NUM), tb>>>(eu, euh, eul, D_DIM, IMOE);
    tsplit_kernel<<<dim3(D_DIM / 32, IMOE / 32, E_NUM), tb>>>(ed, edh, edl, IMOE, D_DIM);

    // ---- shared expert ----
    up_gemm<<<dim3(ISH / 64, T_TOK / 128, 1), 256, GEMM_SMEM>>>(
        xh, xl, sgh, sgl, suh, sul, hsh, hsl, ISH, 0);
    down_gemm<<<dim3(D_DIM / 128, T_TOK / 128, 1), 256, GEMM_SMEM>>>(
        hsh, hsl, sdh, sdl, out, ISH, ISH / 32, 1, 0);

    // ---- routed experts ----
    up_gemm<<<dim3(IMOE / 64, T_TOK / 128, E_NUM), 256, GEMM_SMEM>>>(
        xh, xl, egh, egl, euh, eul, heh, hel, IMOE, 1);
    down_gemm<<<dim3(D_DIM / 128, T_TOK / 128, E_NUM), 256, GEMM_SMEM>>>(
        heh, hel, edh, edl, out, IMOE, IMOE / 32, 2, 1);
}